// round 5
// baseline (speedup 1.0000x reference)
#include <cuda_runtime.h>
#include <cuda_bf16.h>
#include <math.h>

// Problem constants (fixed by the dataset)
#define MAX_NODES 50000
#define DHID1 32
#define DHID2 64
#define DIN   9
#define NAXIS 8
#define NDESC (DHID2 * NAXIS)   // 512

// Scratch: segment-sum accumulator, axis-major: [node][axis(3)][64]
__device__ __align__(16) float g_sum[(size_t)MAX_NODES * 192];
__device__ float g_cnt[MAX_NODES];

// ---------------------------------------------------------------------------
// helpers
// ---------------------------------------------------------------------------
__device__ __forceinline__ float fast_tanh(float x) {
    // accurate (~1e-6 rel) tanh: EX2 + RCP path, clamp avoids overflow
    float xc = fminf(fmaxf(x, -9.0f), 9.0f);
    float e  = __expf(2.0f * xc);
    return __fdividef(e - 1.0f, e + 1.0f);
}

__device__ __forceinline__ void red_add_v4(float* p, float a, float b, float c, float d) {
    asm volatile("red.global.add.v4.f32 [%0], {%1, %2, %3, %4};"
                 :: "l"(p), "f"(a), "f"(b), "f"(c), "f"(d) : "memory");
}

// ---------------------------------------------------------------------------
// zero scratch
// ---------------------------------------------------------------------------
__global__ void zero_kernel(float* p, long n) {
    long i = (long)blockIdx.x * blockDim.x + threadIdx.x;
    long stride = (long)gridDim.x * blockDim.x;
    for (; i < n; i += stride) p[i] = 0.0f;
}

// ---------------------------------------------------------------------------
// Phase A: per-env MLP + scatter (segment sum with vector RED atomics)
// ---------------------------------------------------------------------------
__global__ __launch_bounds__(256)
void env_mlp_scatter(const float* __restrict__ env_vec,
                     const float* __restrict__ atom_attr,
                     const int*   __restrict__ env_index,
                     const float* __restrict__ W1, const float* __restrict__ B1,
                     const float* __restrict__ W2, const float* __restrict__ B2,
                     const float* __restrict__ W3, const float* __restrict__ B3,
                     int n_env)
{
    __shared__ __align__(16) float sW1[DIN * DHID1];
    __shared__ __align__(16) float sW2[DHID1 * DHID2];
    __shared__ __align__(16) float sW3[DHID2 * DHID2];
    __shared__ float sB1[DHID1], sB2[DHID2], sB3[DHID2];

    for (int i = threadIdx.x; i < DIN * DHID1;   i += blockDim.x) sW1[i] = W1[i];
    for (int i = threadIdx.x; i < DHID1 * DHID2; i += blockDim.x) sW2[i] = W2[i];
    for (int i = threadIdx.x; i < DHID2 * DHID2; i += blockDim.x) sW3[i] = W3[i];
    if (threadIdx.x < DHID1) sB1[threadIdx.x] = B1[threadIdx.x];
    if (threadIdx.x < DHID2) { sB2[threadIdx.x] = B2[threadIdx.x]; sB3[threadIdx.x] = B3[threadIdx.x]; }
    __syncthreads();

    int e = blockIdx.x * blockDim.x + threadIdx.x;
    if (e >= n_env) return;

    float vx = env_vec[3 * e + 0];
    float vy = env_vec[3 * e + 1];
    float vz = env_vec[3 * e + 2];
    float r  = sqrtf(vx * vx + vy * vy + vz * vz);

    // smooth cutoff
    float snorm;
    if (r < 3.0f) {
        snorm = 1.0f / r;
    } else if (r < 6.0f) {
        float x = (r - 6.0f) * (-1.0f / 3.0f);
        snorm = (1.0f / r) * (x * x * x * (10.0f + x * (-15.0f + 6.0f * x)) + 1.0f);
    } else {
        snorm = 0.0f;
    }

    int src = env_index[e];
    int dst = env_index[n_env + e];
    float4 as = *(const float4*)(atom_attr + 4 * src);
    float4 ad = *(const float4*)(atom_attr + 4 * dst);

    float in[DIN] = {snorm, as.x, as.y, as.z, as.w, ad.x, ad.y, ad.z, ad.w};

    // ---- layer 1: [9] -> [32] ----
    float h1[DHID1];
    {
        float acc[DHID1];
        #pragma unroll
        for (int j = 0; j < DHID1; j++) acc[j] = sB1[j];
        #pragma unroll
        for (int k = 0; k < DIN; k++) {
            float xk = in[k];
            #pragma unroll
            for (int j = 0; j < DHID1; j += 4) {
                float4 w = *(const float4*)(sW1 + k * DHID1 + j);
                acc[j + 0] = fmaf(xk, w.x, acc[j + 0]);
                acc[j + 1] = fmaf(xk, w.y, acc[j + 1]);
                acc[j + 2] = fmaf(xk, w.z, acc[j + 2]);
                acc[j + 3] = fmaf(xk, w.w, acc[j + 3]);
            }
        }
        #pragma unroll
        for (int j = 0; j < DHID1; j++) h1[j] = fast_tanh(acc[j]);
    }

    // ---- layer 2: [32] -> [64] ----
    float h2[DHID2];
    {
        float acc[DHID2];
        #pragma unroll
        for (int j = 0; j < DHID2; j++) acc[j] = sB2[j];
        #pragma unroll
        for (int k = 0; k < DHID1; k++) {
            float xk = h1[k];
            #pragma unroll
            for (int j = 0; j < DHID2; j += 4) {
                float4 w = *(const float4*)(sW2 + k * DHID2 + j);
                acc[j + 0] = fmaf(xk, w.x, acc[j + 0]);
                acc[j + 1] = fmaf(xk, w.y, acc[j + 1]);
                acc[j + 2] = fmaf(xk, w.z, acc[j + 2]);
                acc[j + 3] = fmaf(xk, w.w, acc[j + 3]);
            }
        }
        #pragma unroll
        for (int j = 0; j < DHID2; j++) h2[j] = fast_tanh(acc[j]);
    }

    // ---- layer 3 (residual): chunks of 16, scatter immediately ----
    float* base = g_sum + (long)dst * 192;
    #pragma unroll
    for (int c = 0; c < DHID2; c += 16) {
        float acc[16];
        #pragma unroll
        for (int jj = 0; jj < 16; jj++) acc[jj] = sB3[c + jj];
        #pragma unroll
        for (int k = 0; k < DHID2; k++) {
            float xk = h2[k];
            #pragma unroll
            for (int jj = 0; jj < 16; jj += 4) {
                float4 w = *(const float4*)(sW3 + k * DHID2 + c + jj);
                acc[jj + 0] = fmaf(xk, w.x, acc[jj + 0]);
                acc[jj + 1] = fmaf(xk, w.y, acc[jj + 1]);
                acc[jj + 2] = fmaf(xk, w.z, acc[jj + 2]);
                acc[jj + 3] = fmaf(xk, w.w, acc[jj + 3]);
            }
        }
        float h3[16];
        #pragma unroll
        for (int jj = 0; jj < 16; jj++) h3[jj] = fast_tanh(acc[jj]) + h2[c + jj];

        // scatter outer product slice: axis-major [3][64]
        #pragma unroll
        for (int a3 = 0; a3 < 3; a3++) {
            float va = (a3 == 0) ? vx : ((a3 == 1) ? vy : vz);
            #pragma unroll
            for (int q = 0; q < 16; q += 4) {
                red_add_v4(base + a3 * 64 + c + q,
                           h3[q + 0] * va, h3[q + 1] * va,
                           h3[q + 2] * va, h3[q + 3] * va);
            }
        }
    }
    atomicAdd(g_cnt + dst, 1.0f);
}

// ---------------------------------------------------------------------------
// Phase B: per-node mean + self outer product (first NAXIS cols) -> node_desc
// ---------------------------------------------------------------------------
__global__ __launch_bounds__(256)
void node_desc_kernel(float* __restrict__ node_desc, int n_nodes)
{
    __shared__ float sa[4 * 192];   // 4 nodes per block, axis-major [3][64]
    int node0 = blockIdx.x * 4;
    long gbase = (long)node0 * 192;

    for (int i = threadIdx.x; i < 4 * 192; i += 256) {
        int node = node0 + i / 192;
        float v = 0.0f;
        if (node < n_nodes) {
            float cnt = fmaxf(g_cnt[node], 1.0f);
            v = g_sum[gbase + i] / cnt;
        }
        sa[i] = v;
    }
    __syncthreads();

    int local = threadIdx.x >> 6;        // 0..3
    int d     = threadIdx.x & 63;        // 0..63
    int node  = node0 + local;
    if (node >= n_nodes) return;

    const float* a = sa + local * 192;
    float a0 = a[0 * 64 + d];
    float a1 = a[1 * 64 + d];
    float a2 = a[2 * 64 + d];

    float o[NAXIS];
    #pragma unroll
    for (int e2 = 0; e2 < NAXIS; e2++) {
        o[e2] = a0 * a[0 * 64 + e2] + a1 * a[1 * 64 + e2] + a2 * a[2 * 64 + e2];
    }

    float4* dst = (float4*)(node_desc + (long)node * NDESC + d * NAXIS);
    dst[0] = make_float4(o[0], o[1], o[2], o[3]);
    dst[1] = make_float4(o[4], o[5], o[6], o[7]);
}

// ---------------------------------------------------------------------------
// Phase C: edge_desc[e] = node_desc[src] + node_desc[dst]
// ---------------------------------------------------------------------------
__global__ __launch_bounds__(256)
void edge_desc_kernel(const int* __restrict__ edge_index,
                      const float* __restrict__ node_desc,
                      float* __restrict__ edge_desc,
                      int n_edges)
{
    int t = threadIdx.x;
    int eidx = blockIdx.x * 2 + (t >> 7);   // 2 edges per block, 128 threads each
    if (eidx >= n_edges) return;
    int j = t & 127;                        // float4 index within the 512-row

    int s = edge_index[eidx];
    int d = edge_index[n_edges + eidx];

    float4 x = ((const float4*)(node_desc + (long)s * NDESC))[j];
    float4 y = ((const float4*)(node_desc + (long)d * NDESC))[j];
    float4 rr = make_float4(x.x + y.x, x.y + y.y, x.z + y.z, x.w + y.w);
    ((float4*)(edge_desc + (long)eidx * NDESC))[j] = rr;
}

// ---------------------------------------------------------------------------
// launch
// ---------------------------------------------------------------------------
extern "C" void kernel_launch(void* const* d_in, const int* in_sizes, int n_in,
                              void* d_out, int out_size)
{
    const float* env_vec   = (const float*)d_in[0];
    const float* atom_attr = (const float*)d_in[1];
    const int*   env_index = (const int*)  d_in[2];
    const int*   edge_index= (const int*)  d_in[3];
    const float* W1 = (const float*)d_in[4];
    const float* B1 = (const float*)d_in[5];
    const float* W2 = (const float*)d_in[6];
    const float* B2 = (const float*)d_in[7];
    const float* W3 = (const float*)d_in[8];
    const float* B3 = (const float*)d_in[9];

    int n_env   = in_sizes[0] / 3;
    int n_nodes = in_sizes[1] / 4;
    int n_edges = in_sizes[3] / 2;

    float* node_desc = (float*)d_out;
    float* edge_desc = (float*)d_out + (long)n_nodes * NDESC;

    // resolve scratch symbol addresses (pure queries; not stream ops)
    float* sum_ptr = nullptr;
    float* cnt_ptr = nullptr;
    cudaGetSymbolAddress((void**)&sum_ptr, g_sum);
    cudaGetSymbolAddress((void**)&cnt_ptr, g_cnt);

    long n_sum = (long)n_nodes * 192;
    zero_kernel<<<2048, 256>>>(sum_ptr, n_sum);
    zero_kernel<<<128, 256>>>(cnt_ptr, (long)n_nodes);

    env_mlp_scatter<<<(n_env + 255) / 256, 256>>>(
        env_vec, atom_attr, env_index, W1, B1, W2, B2, W3, B3, n_env);

    node_desc_kernel<<<(n_nodes + 3) / 4, 256>>>(node_desc, n_nodes);

    edge_desc_kernel<<<(n_edges + 1) / 2, 256>>>(edge_index, node_desc, edge_desc, n_edges);
}

// round 6
// speedup vs baseline: 1.4595x; 1.4595x over previous
#include <cuda_runtime.h>
#include <cuda_bf16.h>
#include <math.h>

// Problem constants (fixed by the dataset)
#define MAX_NODES 50000
#define DHID1 32
#define DHID2 64
#define DIN   9
#define NAXIS 8
#define NDESC (DHID2 * NAXIS)   // 512

typedef unsigned long long ull_t;

// Scratch: segment-sum accumulator, axis-major: [node][axis(3)][64]
__device__ __align__(16) float g_sum[(size_t)MAX_NODES * 192];
__device__ float g_cnt[MAX_NODES];

// ---------------------------------------------------------------------------
// helpers
// ---------------------------------------------------------------------------
__device__ __forceinline__ float fast_tanh(float x) {
    // accurate (~1e-6 rel) tanh: EX2 + RCP path, clamp avoids overflow
    float xc = fminf(fmaxf(x, -9.0f), 9.0f);
    float e  = __expf(2.0f * xc);
    return __fdividef(e - 1.0f, e + 1.0f);
}

__device__ __forceinline__ void red_add_v4(float* p, float a, float b, float c, float d) {
    asm volatile("red.global.add.v4.f32 [%0], {%1, %2, %3, %4};"
                 :: "l"(p), "f"(a), "f"(b), "f"(c), "f"(d) : "memory");
}

// packed-f32x2 helpers (FFMA2 — only reachable via PTX fma.rn.f32x2)
__device__ __forceinline__ ull_t pack2(float x) {
    ull_t r;
    asm("mov.b64 %0, {%1, %1};" : "=l"(r) : "f"(x));
    return r;
}
__device__ __forceinline__ void fma2(ull_t& acc, ull_t a, ull_t b) {
    asm("fma.rn.f32x2 %0, %1, %2, %0;" : "+l"(acc) : "l"(a), "l"(b));
}
__device__ __forceinline__ float2 unpack2(ull_t v) {
    float2 f;
    asm("mov.b64 {%0, %1}, %2;" : "=f"(f.x), "=f"(f.y) : "l"(v));
    return f;
}

// ---------------------------------------------------------------------------
// zero scratch
// ---------------------------------------------------------------------------
__global__ void zero_kernel(float* p, long n) {
    long i = (long)blockIdx.x * blockDim.x + threadIdx.x;
    long stride = (long)gridDim.x * blockDim.x;
    for (; i < n; i += stride) p[i] = 0.0f;
}

// ---------------------------------------------------------------------------
// Phase A: per-env MLP (packed f32x2) + scatter (vector RED atomics)
// ---------------------------------------------------------------------------
__global__ __launch_bounds__(256)
void env_mlp_scatter(const float* __restrict__ env_vec,
                     const float* __restrict__ atom_attr,
                     const int*   __restrict__ env_index,
                     const float* __restrict__ W1, const float* __restrict__ B1,
                     const float* __restrict__ W2, const float* __restrict__ B2,
                     const float* __restrict__ W3, const float* __restrict__ B3,
                     int n_env)
{
    __shared__ __align__(16) float sW1[DIN * DHID1];
    __shared__ __align__(16) float sW2[DHID1 * DHID2];
    __shared__ __align__(16) float sW3[DHID2 * DHID2];
    __shared__ __align__(16) float sB1[DHID1];
    __shared__ __align__(16) float sB2[DHID2];
    __shared__ __align__(16) float sB3[DHID2];

    for (int i = threadIdx.x; i < DIN * DHID1;   i += blockDim.x) sW1[i] = W1[i];
    for (int i = threadIdx.x; i < DHID1 * DHID2; i += blockDim.x) sW2[i] = W2[i];
    for (int i = threadIdx.x; i < DHID2 * DHID2; i += blockDim.x) sW3[i] = W3[i];
    if (threadIdx.x < DHID1) sB1[threadIdx.x] = B1[threadIdx.x];
    if (threadIdx.x < DHID2) { sB2[threadIdx.x] = B2[threadIdx.x]; sB3[threadIdx.x] = B3[threadIdx.x]; }
    __syncthreads();

    int e = blockIdx.x * blockDim.x + threadIdx.x;
    if (e >= n_env) return;

    float vx = env_vec[3 * e + 0];
    float vy = env_vec[3 * e + 1];
    float vz = env_vec[3 * e + 2];
    float r  = sqrtf(vx * vx + vy * vy + vz * vz);

    // smooth cutoff
    float snorm;
    if (r < 3.0f) {
        snorm = 1.0f / r;
    } else if (r < 6.0f) {
        float x = (r - 6.0f) * (-1.0f / 3.0f);
        snorm = (1.0f / r) * (x * x * x * (10.0f + x * (-15.0f + 6.0f * x)) + 1.0f);
    } else {
        snorm = 0.0f;
    }

    int src = env_index[e];
    int dst = env_index[n_env + e];
    float4 as = *(const float4*)(atom_attr + 4 * src);
    float4 ad = *(const float4*)(atom_attr + 4 * dst);

    float in[DIN] = {snorm, as.x, as.y, as.z, as.w, ad.x, ad.y, ad.z, ad.w};

    // ---- layer 1: [9] -> [32], packed ----
    float h1[DHID1];
    {
        ull_t acc[16];
        #pragma unroll
        for (int j = 0; j < 16; j++) acc[j] = *(const ull_t*)(sB1 + 2 * j);
        #pragma unroll
        for (int k = 0; k < DIN; k++) {
            ull_t x2 = pack2(in[k]);
            #pragma unroll
            for (int jj = 0; jj < 8; jj++) {
                ulonglong2 w = *(const ulonglong2*)(sW1 + k * DHID1 + jj * 4);
                fma2(acc[2 * jj + 0], x2, w.x);
                fma2(acc[2 * jj + 1], x2, w.y);
            }
        }
        #pragma unroll
        for (int j = 0; j < 16; j++) {
            float2 t = unpack2(acc[j]);
            h1[2 * j + 0] = fast_tanh(t.x);
            h1[2 * j + 1] = fast_tanh(t.y);
        }
    }

    // ---- layer 2: [32] -> [64], packed ----
    float h2[DHID2];
    {
        ull_t acc[32];
        #pragma unroll
        for (int j = 0; j < 32; j++) acc[j] = *(const ull_t*)(sB2 + 2 * j);
        #pragma unroll
        for (int k = 0; k < DHID1; k++) {
            ull_t x2 = pack2(h1[k]);
            #pragma unroll
            for (int jj = 0; jj < 16; jj++) {
                ulonglong2 w = *(const ulonglong2*)(sW2 + k * DHID2 + jj * 4);
                fma2(acc[2 * jj + 0], x2, w.x);
                fma2(acc[2 * jj + 1], x2, w.y);
            }
        }
        #pragma unroll
        for (int j = 0; j < 32; j++) {
            float2 t = unpack2(acc[j]);
            h2[2 * j + 0] = fast_tanh(t.x);
            h2[2 * j + 1] = fast_tanh(t.y);
        }
    }

    // ---- layer 3 (residual): chunks of 32 outputs, packed; scatter per chunk ----
    float* base = g_sum + (long)dst * 192;
    #pragma unroll
    for (int c = 0; c < DHID2; c += 32) {
        ull_t acc[16];
        #pragma unroll
        for (int j = 0; j < 16; j++) acc[j] = *(const ull_t*)(sB3 + c + 2 * j);
        #pragma unroll
        for (int k = 0; k < DHID2; k++) {
            ull_t x2 = pack2(h2[k]);
            #pragma unroll
            for (int jj = 0; jj < 8; jj++) {
                ulonglong2 w = *(const ulonglong2*)(sW3 + k * DHID2 + c + jj * 4);
                fma2(acc[2 * jj + 0], x2, w.x);
                fma2(acc[2 * jj + 1], x2, w.y);
            }
        }
        float h3[32];
        #pragma unroll
        for (int j = 0; j < 16; j++) {
            float2 t = unpack2(acc[j]);
            h3[2 * j + 0] = fast_tanh(t.x) + h2[c + 2 * j + 0];
            h3[2 * j + 1] = fast_tanh(t.y) + h2[c + 2 * j + 1];
        }

        // scatter outer-product slice: axis-major [3][64]
        #pragma unroll
        for (int a3 = 0; a3 < 3; a3++) {
            float va = (a3 == 0) ? vx : ((a3 == 1) ? vy : vz);
            #pragma unroll
            for (int q = 0; q < 32; q += 4) {
                red_add_v4(base + a3 * 64 + c + q,
                           h3[q + 0] * va, h3[q + 1] * va,
                           h3[q + 2] * va, h3[q + 3] * va);
            }
        }
    }
    atomicAdd(g_cnt + dst, 1.0f);
}

// ---------------------------------------------------------------------------
// Phase B: per-node mean + self outer product (first NAXIS cols) -> node_desc
// ---------------------------------------------------------------------------
__global__ __launch_bounds__(256)
void node_desc_kernel(float* __restrict__ node_desc, int n_nodes)
{
    __shared__ float sa[4 * 192];   // 4 nodes per block, axis-major [3][64]
    int node0 = blockIdx.x * 4;
    long gbase = (long)node0 * 192;

    for (int i = threadIdx.x; i < 4 * 192; i += 256) {
        int node = node0 + i / 192;
        float v = 0.0f;
        if (node < n_nodes) {
            float cnt = fmaxf(g_cnt[node], 1.0f);
            v = g_sum[gbase + i] / cnt;
        }
        sa[i] = v;
    }
    __syncthreads();

    int local = threadIdx.x >> 6;        // 0..3
    int d     = threadIdx.x & 63;        // 0..63
    int node  = node0 + local;
    if (node >= n_nodes) return;

    const float* a = sa + local * 192;
    float a0 = a[0 * 64 + d];
    float a1 = a[1 * 64 + d];
    float a2 = a[2 * 64 + d];

    float o[NAXIS];
    #pragma unroll
    for (int e2 = 0; e2 < NAXIS; e2++) {
        o[e2] = a0 * a[0 * 64 + e2] + a1 * a[1 * 64 + e2] + a2 * a[2 * 64 + e2];
    }

    float4* dst = (float4*)(node_desc + (long)node * NDESC + d * NAXIS);
    dst[0] = make_float4(o[0], o[1], o[2], o[3]);
    dst[1] = make_float4(o[4], o[5], o[6], o[7]);
}

// ---------------------------------------------------------------------------
// Phase C: edge_desc[e] = node_desc[src] + node_desc[dst]
// ---------------------------------------------------------------------------
__global__ __launch_bounds__(256)
void edge_desc_kernel(const int* __restrict__ edge_index,
                      const float* __restrict__ node_desc,
                      float* __restrict__ edge_desc,
                      int n_edges)
{
    int t = threadIdx.x;
    int eidx = blockIdx.x * 2 + (t >> 7);   // 2 edges per block, 128 threads each
    if (eidx >= n_edges) return;
    int j = t & 127;                        // float4 index within the 512-row

    int s = edge_index[eidx];
    int d = edge_index[n_edges + eidx];

    float4 x = ((const float4*)(node_desc + (long)s * NDESC))[j];
    float4 y = ((const float4*)(node_desc + (long)d * NDESC))[j];
    float4 rr = make_float4(x.x + y.x, x.y + y.y, x.z + y.z, x.w + y.w);
    ((float4*)(edge_desc + (long)eidx * NDESC))[j] = rr;
}

// ---------------------------------------------------------------------------
// launch
// ---------------------------------------------------------------------------
extern "C" void kernel_launch(void* const* d_in, const int* in_sizes, int n_in,
                              void* d_out, int out_size)
{
    const float* env_vec   = (const float*)d_in[0];
    const float* atom_attr = (const float*)d_in[1];
    const int*   env_index = (const int*)  d_in[2];
    const int*   edge_index= (const int*)  d_in[3];
    const float* W1 = (const float*)d_in[4];
    const float* B1 = (const float*)d_in[5];
    const float* W2 = (const float*)d_in[6];
    const float* B2 = (const float*)d_in[7];
    const float* W3 = (const float*)d_in[8];
    const float* B3 = (const float*)d_in[9];

    int n_env   = in_sizes[0] / 3;
    int n_nodes = in_sizes[1] / 4;
    int n_edges = in_sizes[3] / 2;

    float* node_desc = (float*)d_out;
    float* edge_desc = (float*)d_out + (long)n_nodes * NDESC;

    // resolve scratch symbol addresses (pure queries; not stream ops)
    float* sum_ptr = nullptr;
    float* cnt_ptr = nullptr;
    cudaGetSymbolAddress((void**)&sum_ptr, g_sum);
    cudaGetSymbolAddress((void**)&cnt_ptr, g_cnt);

    long n_sum = (long)n_nodes * 192;
    zero_kernel<<<2048, 256>>>(sum_ptr, n_sum);
    zero_kernel<<<128, 256>>>(cnt_ptr, (long)n_nodes);

    env_mlp_scatter<<<(n_env + 255) / 256, 256>>>(
        env_vec, atom_attr, env_index, W1, B1, W2, B2, W3, B3, n_env);

    node_desc_kernel<<<(n_nodes + 3) / 4, 256>>>(node_desc, n_nodes);

    edge_desc_kernel<<<(n_edges + 1) / 2, 256>>>(edge_index, node_desc, edge_desc, n_edges);
}